// round 7
// baseline (speedup 1.0000x reference)
#include <cuda_runtime.h>

#define TPB 128

struct CamParams {
    float c2w[9];
    float t[3];
    float Kinv[9];
    float mult;
};

__global__ void __launch_bounds__(TPB, 13)
mono_gaussian_adapter_kernel(
    const float* __restrict__ ext,        // (B,1,4,4)
    const float* __restrict__ intr,       // (B,1,3,3)
    const float* __restrict__ coords,     // (B,N,2)
    const float* __restrict__ depths,     // (B,N)
    const float* __restrict__ opac,       // (B,N)
    const float* __restrict__ rg,         // (B,N,19)
    const unsigned int* __restrict__ hptr,
    const unsigned int* __restrict__ wptr,
    float* __restrict__ out,
    int N)
{
    // Staging buffer: input rg (19T floats), then reused for cov staging (9T floats).
    __shared__ __align__(16) float buf[TPB * 19];
    __shared__ CamParams cam;
    const int b   = blockIdx.y;
    const int tid = threadIdx.x;

    // 32-bit indexing throughout (max offset = B*N*12 floats < 2^31).
    const int n    = blockIdx.x * TPB + tid;
    const int idx0 = b * N + blockIdx.x * TPB;
    const int idx  = idx0 + tid;
    const int BN   = (int)gridDim.y * N;
    const bool full = (blockIdx.x * TPB + TPB) <= N;
    const bool live = n < N;

    float4* buf4 = (float4*)buf;

    // ---- input staging (overlapped with cam computation; one sync covers both) ----
    if (full) {
        const float4* src4 = (const float4*)(rg + (size_t)idx0 * 19);
        for (int j = tid; j < TPB * 19 / 4; j += TPB) buf4[j] = src4[j];
    }

    if (tid == 0) {
        const float* E = ext + b * 16;
        const float* K = intr + b * 9;
#pragma unroll
        for (int i = 0; i < 3; i++) {
            cam.c2w[i * 3 + 0] = E[i * 4 + 0];
            cam.c2w[i * 3 + 1] = E[i * 4 + 1];
            cam.c2w[i * 3 + 2] = E[i * 4 + 2];
            cam.t[i]           = E[i * 4 + 3];
        }
        float k00 = K[0], k01 = K[1], k02 = K[2];
        float k10 = K[3], k11 = K[4], k12 = K[5];
        float k20 = K[6], k21 = K[7], k22 = K[8];
        float det = k00 * (k11 * k22 - k12 * k21)
                  - k01 * (k10 * k22 - k12 * k20)
                  + k02 * (k10 * k21 - k11 * k20);
        float id = 1.0f / det;
        cam.Kinv[0] = (k11 * k22 - k12 * k21) * id;
        cam.Kinv[1] = (k02 * k21 - k01 * k22) * id;
        cam.Kinv[2] = (k01 * k12 - k02 * k11) * id;
        cam.Kinv[3] = (k12 * k20 - k10 * k22) * id;
        cam.Kinv[4] = (k00 * k22 - k02 * k20) * id;
        cam.Kinv[5] = (k02 * k10 - k00 * k12) * id;
        cam.Kinv[6] = (k10 * k21 - k11 * k20) * id;
        cam.Kinv[7] = (k01 * k20 - k00 * k21) * id;
        cam.Kinv[8] = (k00 * k11 - k01 * k10) * id;

        unsigned hv = hptr[0], wv = wptr[0];
        float hf = (hv < 100000u) ? (float)hv : __uint_as_float(hv);
        float wf = (wv < 100000u) ? (float)wv : __uint_as_float(wv);
        float px = 1.0f / wf, py = 1.0f / hf;
        float det2 = k00 * k11 - k01 * k10;
        cam.mult = 0.1f * ((k11 * px - k01 * py) + (-k10 * px + k00 * py)) / det2;
    }
    __syncthreads();

    // ---- output section pointers ----
    float* means_o = out;                 // BN*3
    float* cov_o   = out + BN * 3;        // BN*9
    float* har_o   = out + BN * 12;       // BN*12
    float* op_o    = out + BN * 24;       // BN*1
    float* sc_o    = out + BN * 25;       // BN*3
    float* rot_o   = out + BN * 28;       // BN*4

    // Per-thread scalar inputs (coalesced already)
    float2 uv = make_float2(0.f, 0.f);
    float depth = 0.f, op = 0.f;
    if (live) {
        uv    = ((const float2*)coords)[idx];
        depth = depths[idx];
        op    = opac[idx];
    }

    // ---- rg values: scales+quat into registers; SH read just-in-time from smem ----
    float g0, g1, g2, qw, qx, qy, qz;
    const float* grow_s = buf + tid * 19;                 // smem row (full blocks)
    const float* grow_g = rg + (size_t)idx * 19;          // gmem row (tail blocks)
    if (full) {
        g0 = grow_s[0]; g1 = grow_s[1]; g2 = grow_s[2];
        qw = grow_s[3]; qx = grow_s[4]; qy = grow_s[5]; qz = grow_s[6];
    } else if (live) {
        g0 = grow_g[0]; g1 = grow_g[1]; g2 = grow_g[2];
        qw = grow_g[3]; qx = grow_g[4]; qy = grow_g[5]; qz = grow_g[6];
    } else {
        g0 = g1 = g2 = 0.f; qw = 1.f; qx = qy = qz = 0.f;
    }

    // ---- scales ----
    float dm = depth * cam.mult;
    float sc0 = (0.5f + 14.5f / (1.0f + __expf(-g0))) * dm;
    float sc1 = (0.5f + 14.5f / (1.0f + __expf(-g1))) * dm;
    float sc2 = (0.5f + 14.5f / (1.0f + __expf(-g2))) * dm;

    // ---- quaternion normalize ----
    float qn = sqrtf(qw * qw + qx * qx + qy * qy + qz * qz) + 1e-8f;
    float qinv = 1.0f / qn;
    qw *= qinv; qx *= qinv; qy *= qinv; qz *= qinv;

    // ---- harmonics: read SH from smem/gmem, transform, STORE DIRECT (STG.128, 16B-aligned) ----
    {
        const int pr[3] = {1, 2, 0};
        float4* dh = (float4*)(har_o + (size_t)idx * 12);
#pragma unroll
        for (int c = 0; c < 3; c++) {
            float h0, s1, s2, s3;
            if (full) {
                h0 = grow_s[7 + c * 4 + 0];
                s1 = grow_s[7 + c * 4 + 1] * 0.025f;
                s2 = grow_s[7 + c * 4 + 2] * 0.025f;
                s3 = grow_s[7 + c * 4 + 3] * 0.025f;
            } else if (live) {
                h0 = grow_g[7 + c * 4 + 0];
                s1 = grow_g[7 + c * 4 + 1] * 0.025f;
                s2 = grow_g[7 + c * 4 + 2] * 0.025f;
                s3 = grow_g[7 + c * 4 + 3] * 0.025f;
            } else {
                h0 = s1 = s2 = s3 = 0.f;
            }
            float hv[3];
#pragma unroll
            for (int i = 0; i < 3; i++) {
                int ri = pr[i];
                hv[i] = cam.c2w[ri * 3 + 1] * s1
                      + cam.c2w[ri * 3 + 2] * s2
                      + cam.c2w[ri * 3 + 0] * s3;
            }
            if (live) dh[c] = make_float4(h0, hv[0], hv[1], hv[2]);
        }
    }

    // ---- direct stores: opacity, rotations, means, scales ----
    if (live) {
        op_o[idx] = op;
        ((float4*)rot_o)[idx] = make_float4(qw, qx, qy, qz);

        // means
        float d0 = cam.Kinv[0] * uv.x + cam.Kinv[1] * uv.y + cam.Kinv[2];
        float d1 = cam.Kinv[3] * uv.x + cam.Kinv[4] * uv.y + cam.Kinv[5];
        float d2 = cam.Kinv[6] * uv.x + cam.Kinv[7] * uv.y + cam.Kinv[8];
        float rn = rsqrtf(d0 * d0 + d1 * d1 + d2 * d2);
        d0 *= rn; d1 *= rn; d2 *= rn;
#pragma unroll
        for (int i = 0; i < 3; i++)
            means_o[(size_t)idx * 3 + i] = cam.t[i] + (cam.c2w[i * 3 + 0] * d0
                                                      + cam.c2w[i * 3 + 1] * d1
                                                      + cam.c2w[i * 3 + 2] * d2) * depth;
        sc_o[(size_t)idx * 3 + 0] = sc0;
        sc_o[(size_t)idx * 3 + 1] = sc1;
        sc_o[(size_t)idx * 3 + 2] = sc2;
    }

    // ---- cov = (W R diag(s)) (W R diag(s))^T ----
    float R[9];
    R[0] = 1.f - 2.f * (qy * qy + qz * qz);
    R[1] = 2.f * (qx * qy - qw * qz);
    R[2] = 2.f * (qx * qz + qw * qy);
    R[3] = 2.f * (qx * qy + qw * qz);
    R[4] = 1.f - 2.f * (qx * qx + qz * qz);
    R[5] = 2.f * (qy * qz - qw * qx);
    R[6] = 2.f * (qx * qz - qw * qy);
    R[7] = 2.f * (qy * qz + qw * qx);
    R[8] = 1.f - 2.f * (qx * qx + qy * qy);

    float T[9];
#pragma unroll
    for (int i = 0; i < 3; i++) {
        T[i * 3 + 0] = (cam.c2w[i * 3 + 0] * R[0] + cam.c2w[i * 3 + 1] * R[3]
                      + cam.c2w[i * 3 + 2] * R[6]) * sc0;
        T[i * 3 + 1] = (cam.c2w[i * 3 + 0] * R[1] + cam.c2w[i * 3 + 1] * R[4]
                      + cam.c2w[i * 3 + 2] * R[7]) * sc1;
        T[i * 3 + 2] = (cam.c2w[i * 3 + 0] * R[2] + cam.c2w[i * 3 + 1] * R[5]
                      + cam.c2w[i * 3 + 2] * R[8]) * sc2;
    }
    float cov[9];
#pragma unroll
    for (int i = 0; i < 3; i++)
#pragma unroll
        for (int j = 0; j <= i; j++) {
            float v = T[i * 3 + 0] * T[j * 3 + 0]
                    + T[i * 3 + 1] * T[j * 3 + 1]
                    + T[i * 3 + 2] * T[j * 3 + 2];
            cov[i * 3 + j] = v;
            cov[j * 3 + i] = v;
        }

    if (full) {
        // cov staged (scalar stride-36B direct would be 3x the wavefronts; float4 misaligned)
        __syncthreads();   // all smem input reads complete; safe to overwrite buf
#pragma unroll
        for (int i = 0; i < 9; i++) buf[tid * 9 + i] = cov[i];   // stride 9 (odd): conflict-free
        __syncthreads();
        const float4* s4 = (const float4*)buf;
        float4* dc = (float4*)(cov_o + (size_t)idx0 * 9);
        for (int j = tid; j < TPB * 9 / 4; j += TPB) dc[j] = s4[j];
    } else if (live) {
#pragma unroll
        for (int i = 0; i < 9; i++) cov_o[(size_t)idx * 9 + i] = cov[i];
    }
}

extern "C" void kernel_launch(void* const* d_in, const int* in_sizes, int n_in,
                              void* d_out, int out_size)
{
    const float* ext    = (const float*)d_in[0];
    const float* intr   = (const float*)d_in[1];
    const float* coords = (const float*)d_in[2];
    const float* depths = (const float*)d_in[3];
    const float* opac   = (const float*)d_in[4];
    const float* rg     = (const float*)d_in[5];
    const unsigned int* hptr = (const unsigned int*)d_in[6];
    const unsigned int* wptr = (const unsigned int*)d_in[7];
    float* out = (float*)d_out;

    const int B = in_sizes[0] / 16;            // extrinsics: B*1*4*4
    const int N = in_sizes[3] / B;             // depths: B*N

    dim3 grid((N + TPB - 1) / TPB, B);
    mono_gaussian_adapter_kernel<<<grid, TPB>>>(
        ext, intr, coords, depths, opac, rg, hptr, wptr, out, N);
}

// round 8
// speedup vs baseline: 1.0464x; 1.0464x over previous
#include <cuda_runtime.h>

#define TPB 128

struct CamParams {
    float c2w[9];
    float t[3];
    float Kinv[9];
    float mult;
};

__global__ void __launch_bounds__(TPB, 12)
mono_gaussian_adapter_kernel(
    const float* __restrict__ ext,        // (B,1,4,4)
    const float* __restrict__ intr,       // (B,1,3,3)
    const float* __restrict__ coords,     // (B,N,2)
    const float* __restrict__ depths,     // (B,N)
    const float* __restrict__ opac,       // (B,N)
    const float* __restrict__ rg,         // (B,N,19)
    const unsigned int* __restrict__ hptr,
    const unsigned int* __restrict__ wptr,
    float* __restrict__ out,
    int N)
{
    // Staging buffer: input rg (19T floats), reused for outputs cov[0,9T) har[9T,21T).
    __shared__ __align__(16) float buf[TPB * 21];
    __shared__ CamParams cam;
    const int b   = blockIdx.y;
    const int tid = threadIdx.x;

    const int n    = blockIdx.x * TPB + tid;
    const int idx0 = b * N + blockIdx.x * TPB;
    const int idx  = idx0 + tid;
    const int BN   = (int)gridDim.y * N;
    const bool full = (blockIdx.x * TPB + TPB) <= N;
    const bool live = n < N;

    float4* buf4 = (float4*)buf;

    // ---- input staging (overlapped with cam computation; one sync covers both) ----
    if (full) {
        const float4* src4 = (const float4*)(rg + (size_t)idx0 * 19);
        for (int j = tid; j < TPB * 19 / 4; j += TPB) buf4[j] = src4[j];
    }

    if (tid == 0) {
        const float* E = ext + b * 16;
        const float* K = intr + b * 9;
#pragma unroll
        for (int i = 0; i < 3; i++) {
            cam.c2w[i * 3 + 0] = E[i * 4 + 0];
            cam.c2w[i * 3 + 1] = E[i * 4 + 1];
            cam.c2w[i * 3 + 2] = E[i * 4 + 2];
            cam.t[i]           = E[i * 4 + 3];
        }
        float k00 = K[0], k01 = K[1], k02 = K[2];
        float k10 = K[3], k11 = K[4], k12 = K[5];
        float k20 = K[6], k21 = K[7], k22 = K[8];
        float det = k00 * (k11 * k22 - k12 * k21)
                  - k01 * (k10 * k22 - k12 * k20)
                  + k02 * (k10 * k21 - k11 * k20);
        float id = 1.0f / det;
        cam.Kinv[0] = (k11 * k22 - k12 * k21) * id;
        cam.Kinv[1] = (k02 * k21 - k01 * k22) * id;
        cam.Kinv[2] = (k01 * k12 - k02 * k11) * id;
        cam.Kinv[3] = (k12 * k20 - k10 * k22) * id;
        cam.Kinv[4] = (k00 * k22 - k02 * k20) * id;
        cam.Kinv[5] = (k02 * k10 - k00 * k12) * id;
        cam.Kinv[6] = (k10 * k21 - k11 * k20) * id;
        cam.Kinv[7] = (k01 * k20 - k00 * k21) * id;
        cam.Kinv[8] = (k00 * k11 - k01 * k10) * id;

        unsigned hv = hptr[0], wv = wptr[0];
        float hf = (hv < 100000u) ? (float)hv : __uint_as_float(hv);
        float wf = (wv < 100000u) ? (float)wv : __uint_as_float(wv);
        float px = 1.0f / wf, py = 1.0f / hf;
        float det2 = k00 * k11 - k01 * k10;
        cam.mult = 0.1f * ((k11 * px - k01 * py) + (-k10 * px + k00 * py)) / det2;
    }
    __syncthreads();

    // ---- output section pointers ----
    float* means_o = out;                 // BN*3
    float* cov_o   = out + BN * 3;        // BN*9
    float* har_o   = out + BN * 12;       // BN*12
    float* op_o    = out + BN * 24;       // BN*1
    float* sc_o    = out + BN * 25;       // BN*3
    float* rot_o   = out + BN * 28;       // BN*4

    // Per-thread scalar inputs (coalesced already)
    float2 uv = make_float2(0.f, 0.f);
    float depth = 0.f, op = 0.f;
    if (live) {
        uv    = ((const float2*)coords)[idx];
        depth = depths[idx];
        op    = opac[idx];
    }

    // ---- rg: scales+quat to registers; SH read just-in-time ----
    float g0, g1, g2, qw, qx, qy, qz;
    const float* grow_s = buf + tid * 19;                 // smem row (full blocks)
    const float* grow_g = rg + (size_t)idx * 19;          // gmem row (tail blocks)
    if (full) {
        g0 = grow_s[0]; g1 = grow_s[1]; g2 = grow_s[2];
        qw = grow_s[3]; qx = grow_s[4]; qy = grow_s[5]; qz = grow_s[6];
    } else if (live) {
        g0 = grow_g[0]; g1 = grow_g[1]; g2 = grow_g[2];
        qw = grow_g[3]; qx = grow_g[4]; qy = grow_g[5]; qz = grow_g[6];
    } else {
        g0 = g1 = g2 = 0.f; qw = 1.f; qx = qy = qz = 0.f;
    }

    // ---- scales ----
    float dm = depth * cam.mult;
    float sc0 = (0.5f + 14.5f / (1.0f + __expf(-g0))) * dm;
    float sc1 = (0.5f + 14.5f / (1.0f + __expf(-g1))) * dm;
    float sc2 = (0.5f + 14.5f / (1.0f + __expf(-g2))) * dm;

    // ---- quaternion normalize ----
    float qn = sqrtf(qw * qw + qx * qx + qy * qy + qz * qz) + 1e-8f;
    float qinv = 1.0f / qn;
    qw *= qinv; qx *= qinv; qy *= qinv; qz *= qinv;

    // ---- harmonics -> registers ----
    float har[12];
    {
        const int pr[3] = {1, 2, 0};
#pragma unroll
        for (int c = 0; c < 3; c++) {
            float h0, s1, s2, s3;
            if (full) {
                h0 = grow_s[7 + c * 4 + 0];
                s1 = grow_s[7 + c * 4 + 1] * 0.025f;
                s2 = grow_s[7 + c * 4 + 2] * 0.025f;
                s3 = grow_s[7 + c * 4 + 3] * 0.025f;
            } else if (live) {
                h0 = grow_g[7 + c * 4 + 0];
                s1 = grow_g[7 + c * 4 + 1] * 0.025f;
                s2 = grow_g[7 + c * 4 + 2] * 0.025f;
                s3 = grow_g[7 + c * 4 + 3] * 0.025f;
            } else {
                h0 = s1 = s2 = s3 = 0.f;
            }
            har[c * 4 + 0] = h0;
#pragma unroll
            for (int i = 0; i < 3; i++) {
                int ri = pr[i];
                har[c * 4 + 1 + i] = cam.c2w[ri * 3 + 1] * s1
                                   + cam.c2w[ri * 3 + 2] * s2
                                   + cam.c2w[ri * 3 + 0] * s3;
            }
        }
    }

    // ---- direct streaming stores: opacity, rotations, means, scales ----
    if (live) {
        __stcs(op_o + idx, op);
        __stcs((float4*)rot_o + idx, make_float4(qw, qx, qy, qz));

        float d0 = cam.Kinv[0] * uv.x + cam.Kinv[1] * uv.y + cam.Kinv[2];
        float d1 = cam.Kinv[3] * uv.x + cam.Kinv[4] * uv.y + cam.Kinv[5];
        float d2 = cam.Kinv[6] * uv.x + cam.Kinv[7] * uv.y + cam.Kinv[8];
        float rn = rsqrtf(d0 * d0 + d1 * d1 + d2 * d2);
        d0 *= rn; d1 *= rn; d2 *= rn;
#pragma unroll
        for (int i = 0; i < 3; i++)
            __stcs(means_o + (size_t)idx * 3 + i,
                   cam.t[i] + (cam.c2w[i * 3 + 0] * d0
                             + cam.c2w[i * 3 + 1] * d1
                             + cam.c2w[i * 3 + 2] * d2) * depth);
        __stcs(sc_o + (size_t)idx * 3 + 0, sc0);
        __stcs(sc_o + (size_t)idx * 3 + 1, sc1);
        __stcs(sc_o + (size_t)idx * 3 + 2, sc2);
    }

    // ---- cov = (W R diag(s)) (W R diag(s))^T ----
    float R[9];
    R[0] = 1.f - 2.f * (qy * qy + qz * qz);
    R[1] = 2.f * (qx * qy - qw * qz);
    R[2] = 2.f * (qx * qz + qw * qy);
    R[3] = 2.f * (qx * qy + qw * qz);
    R[4] = 1.f - 2.f * (qx * qx + qz * qz);
    R[5] = 2.f * (qy * qz - qw * qx);
    R[6] = 2.f * (qx * qz - qw * qy);
    R[7] = 2.f * (qy * qz + qw * qx);
    R[8] = 1.f - 2.f * (qx * qx + qy * qy);

    float T[9];
#pragma unroll
    for (int i = 0; i < 3; i++) {
        T[i * 3 + 0] = (cam.c2w[i * 3 + 0] * R[0] + cam.c2w[i * 3 + 1] * R[3]
                      + cam.c2w[i * 3 + 2] * R[6]) * sc0;
        T[i * 3 + 1] = (cam.c2w[i * 3 + 0] * R[1] + cam.c2w[i * 3 + 1] * R[4]
                      + cam.c2w[i * 3 + 2] * R[7]) * sc1;
        T[i * 3 + 2] = (cam.c2w[i * 3 + 0] * R[2] + cam.c2w[i * 3 + 1] * R[5]
                      + cam.c2w[i * 3 + 2] * R[8]) * sc2;
    }
    float cov[9];
#pragma unroll
    for (int i = 0; i < 3; i++)
#pragma unroll
        for (int j = 0; j <= i; j++) {
            float v = T[i * 3 + 0] * T[j * 3 + 0]
                    + T[i * 3 + 1] * T[j * 3 + 1]
                    + T[i * 3 + 2] * T[j * 3 + 2];
            cov[i * 3 + j] = v;
            cov[j * 3 + i] = v;
        }

    if (full) {
        __syncthreads();   // smem input reads complete; safe to overwrite buf

        // stage cov (scalar, stride 9 odd -> conflict-free)
#pragma unroll
        for (int i = 0; i < 9; i++) buf[tid * 9 + i] = cov[i];
        // stage har (STS.128, float4-stride 3 -> conflict-free)
        {
            float4* h4 = (float4*)(buf + 9 * TPB);
#pragma unroll
            for (int c = 0; c < 3; c++)
                h4[tid * 3 + c] = make_float4(har[c * 4 + 0], har[c * 4 + 1],
                                              har[c * 4 + 2], har[c * 4 + 3]);
        }
        __syncthreads();

        // combined coalesced streaming flush
        const float4* s4 = (const float4*)buf;
        float4* dc = (float4*)(cov_o + (size_t)idx0 * 9);
        for (int j = tid; j < TPB * 9 / 4; j += TPB)  __stcs(dc + j, s4[j]);
        float4* dh = (float4*)(har_o + (size_t)idx0 * 12);
        for (int j = tid; j < TPB * 12 / 4; j += TPB) __stcs(dh + j, s4[TPB * 9 / 4 + j]);
    } else if (live) {
#pragma unroll
        for (int i = 0; i < 9; i++)  __stcs(cov_o + (size_t)idx * 9 + i, cov[i]);
#pragma unroll
        for (int i = 0; i < 12; i++) __stcs(har_o + (size_t)idx * 12 + i, har[i]);
    }
}

extern "C" void kernel_launch(void* const* d_in, const int* in_sizes, int n_in,
                              void* d_out, int out_size)
{
    const float* ext    = (const float*)d_in[0];
    const float* intr   = (const float*)d_in[1];
    const float* coords = (const float*)d_in[2];
    const float* depths = (const float*)d_in[3];
    const float* opac   = (const float*)d_in[4];
    const float* rg     = (const float*)d_in[5];
    const unsigned int* hptr = (const unsigned int*)d_in[6];
    const unsigned int* wptr = (const unsigned int*)d_in[7];
    float* out = (float*)d_out;

    const int B = in_sizes[0] / 16;            // extrinsics: B*1*4*4
    const int N = in_sizes[3] / B;             // depths: B*N

    dim3 grid((N + TPB - 1) / TPB, B);
    mono_gaussian_adapter_kernel<<<grid, TPB>>>(
        ext, intr, coords, depths, opac, rg, hptr, wptr, out, N);
}

// round 9
// speedup vs baseline: 1.2660x; 1.2098x over previous
#include <cuda_runtime.h>
#include <cstdint>

#define TPB 128
#define RG_BYTES (TPB * 19 * 4)

struct CamParams {
    float c2w[9];
    float t[3];
    float Kinv[9];
    float mult;
};

__global__ void __launch_bounds__(TPB, 12)
mono_gaussian_adapter_kernel(
    const float* __restrict__ ext,        // (B,1,4,4)
    const float* __restrict__ intr,       // (B,1,3,3)
    const float* __restrict__ coords,     // (B,N,2)
    const float* __restrict__ depths,     // (B,N)
    const float* __restrict__ opac,       // (B,N)
    const float* __restrict__ rg,         // (B,N,19)
    const unsigned int* __restrict__ hptr,
    const unsigned int* __restrict__ wptr,
    float* __restrict__ out,
    int N)
{
    // Staging buffer: input rg (19T floats) via cp.async.bulk, reused for cov[0,9T) har[9T,21T).
    __shared__ __align__(16) float buf[TPB * 21];
    __shared__ CamParams cam;
    __shared__ __align__(8) unsigned long long mbar;

    const int b   = blockIdx.y;
    const int tid = threadIdx.x;

    const int n    = blockIdx.x * TPB + tid;
    const int idx0 = b * N + blockIdx.x * TPB;
    const int idx  = idx0 + tid;
    const int BN   = (int)gridDim.y * N;
    const bool full = (blockIdx.x * TPB + TPB) <= N;
    const bool live = n < N;

    const uint32_t smem_buf  = (uint32_t)__cvta_generic_to_shared(buf);
    const uint32_t smem_mbar = (uint32_t)__cvta_generic_to_shared(&mbar);

    // ---- kick off bulk DMA of the rg tile ASAP (full blocks) ----
    if (full && tid == 0) {
        asm volatile("mbarrier.init.shared.b64 [%0], 1;" :: "r"(smem_mbar) : "memory");
        asm volatile("fence.proxy.async.shared::cta;" ::: "memory");
        asm volatile("mbarrier.arrive.expect_tx.shared.b64 _, [%0], %1;"
                     :: "r"(smem_mbar), "r"((uint32_t)RG_BYTES) : "memory");
        asm volatile("cp.async.bulk.shared::cta.global.mbarrier::complete_tx::bytes "
                     "[%0], [%1], %2, [%3];"
                     :: "r"(smem_buf), "l"(rg + (size_t)idx0 * 19),
                        "r"((uint32_t)RG_BYTES), "r"(smem_mbar) : "memory");
    }

    // ---- cam computation (overlaps DMA) ----
    if (tid == 0) {
        const float* E = ext + b * 16;
        const float* K = intr + b * 9;
#pragma unroll
        for (int i = 0; i < 3; i++) {
            cam.c2w[i * 3 + 0] = E[i * 4 + 0];
            cam.c2w[i * 3 + 1] = E[i * 4 + 1];
            cam.c2w[i * 3 + 2] = E[i * 4 + 2];
            cam.t[i]           = E[i * 4 + 3];
        }
        float k00 = K[0], k01 = K[1], k02 = K[2];
        float k10 = K[3], k11 = K[4], k12 = K[5];
        float k20 = K[6], k21 = K[7], k22 = K[8];
        float det = k00 * (k11 * k22 - k12 * k21)
                  - k01 * (k10 * k22 - k12 * k20)
                  + k02 * (k10 * k21 - k11 * k20);
        float id = 1.0f / det;
        cam.Kinv[0] = (k11 * k22 - k12 * k21) * id;
        cam.Kinv[1] = (k02 * k21 - k01 * k22) * id;
        cam.Kinv[2] = (k01 * k12 - k02 * k11) * id;
        cam.Kinv[3] = (k12 * k20 - k10 * k22) * id;
        cam.Kinv[4] = (k00 * k22 - k02 * k20) * id;
        cam.Kinv[5] = (k02 * k10 - k00 * k12) * id;
        cam.Kinv[6] = (k10 * k21 - k11 * k20) * id;
        cam.Kinv[7] = (k01 * k20 - k00 * k21) * id;
        cam.Kinv[8] = (k00 * k11 - k01 * k10) * id;

        unsigned hv = hptr[0], wv = wptr[0];
        float hf = (hv < 100000u) ? (float)hv : __uint_as_float(hv);
        float wf = (wv < 100000u) ? (float)wv : __uint_as_float(wv);
        float px = 1.0f / wf, py = 1.0f / hf;
        float det2 = k00 * k11 - k01 * k10;
        cam.mult = 0.1f * ((k11 * px - k01 * py) + (-k10 * px + k00 * py)) / det2;
    }

    // ---- per-thread scalar inputs (LDGs overlap the DMA) ----
    float2 uv = make_float2(0.f, 0.f);
    float depth = 0.f, op = 0.f;
    if (live) {
        uv    = ((const float2*)coords)[idx];
        depth = depths[idx];
        op    = opac[idx];
    }

    __syncthreads();   // cam ready (also orders mbar init for all threads)

    // ---- output section pointers ----
    float* means_o = out;                 // BN*3
    float* cov_o   = out + BN * 3;        // BN*9
    float* har_o   = out + BN * 12;       // BN*12
    float* op_o    = out + BN * 24;       // BN*1
    float* sc_o    = out + BN * 25;       // BN*3
    float* rot_o   = out + BN * 28;       // BN*4

    // ---- rg-independent outputs first: opacity + means (hides DMA latency) ----
    if (live) {
        __stcs(op_o + idx, op);

        float d0 = cam.Kinv[0] * uv.x + cam.Kinv[1] * uv.y + cam.Kinv[2];
        float d1 = cam.Kinv[3] * uv.x + cam.Kinv[4] * uv.y + cam.Kinv[5];
        float d2 = cam.Kinv[6] * uv.x + cam.Kinv[7] * uv.y + cam.Kinv[8];
        float rn = rsqrtf(d0 * d0 + d1 * d1 + d2 * d2);
        d0 *= rn; d1 *= rn; d2 *= rn;
#pragma unroll
        for (int i = 0; i < 3; i++)
            __stcs(means_o + (size_t)idx * 3 + i,
                   cam.t[i] + (cam.c2w[i * 3 + 0] * d0
                             + cam.c2w[i * 3 + 1] * d1
                             + cam.c2w[i * 3 + 2] * d2) * depth);
    }

    // ---- wait for the rg tile, then consume ----
    if (full) {
        asm volatile(
            "{\n\t.reg .pred p;\n\t"
            "WAIT_%=:\n\t"
            "mbarrier.try_wait.parity.acquire.cta.shared::cta.b64 p, [%0], %1, 0x989680;\n\t"
            "@p bra DONE_%=;\n\t"
            "bra WAIT_%=;\n\t"
            "DONE_%=:\n\t}"
            :: "r"(smem_mbar), "r"(0u) : "memory");
    }

    float g0, g1, g2, qw, qx, qy, qz;
    const float* grow_s = buf + tid * 19;                 // smem row (full blocks)
    const float* grow_g = rg + (size_t)idx * 19;          // gmem row (tail blocks)
    if (full) {
        g0 = grow_s[0]; g1 = grow_s[1]; g2 = grow_s[2];
        qw = grow_s[3]; qx = grow_s[4]; qy = grow_s[5]; qz = grow_s[6];
    } else if (live) {
        g0 = grow_g[0]; g1 = grow_g[1]; g2 = grow_g[2];
        qw = grow_g[3]; qx = grow_g[4]; qy = grow_g[5]; qz = grow_g[6];
    } else {
        g0 = g1 = g2 = 0.f; qw = 1.f; qx = qy = qz = 0.f;
    }

    // ---- scales ----
    float dm = depth * cam.mult;
    float sc0 = (0.5f + 14.5f / (1.0f + __expf(-g0))) * dm;
    float sc1 = (0.5f + 14.5f / (1.0f + __expf(-g1))) * dm;
    float sc2 = (0.5f + 14.5f / (1.0f + __expf(-g2))) * dm;

    // ---- quaternion normalize ----
    float qn = sqrtf(qw * qw + qx * qx + qy * qy + qz * qz) + 1e-8f;
    float qinv = 1.0f / qn;
    qw *= qinv; qx *= qinv; qy *= qinv; qz *= qinv;

    // ---- harmonics -> registers ----
    float har[12];
    {
        const int pr[3] = {1, 2, 0};
#pragma unroll
        for (int c = 0; c < 3; c++) {
            float h0, s1, s2, s3;
            if (full) {
                h0 = grow_s[7 + c * 4 + 0];
                s1 = grow_s[7 + c * 4 + 1] * 0.025f;
                s2 = grow_s[7 + c * 4 + 2] * 0.025f;
                s3 = grow_s[7 + c * 4 + 3] * 0.025f;
            } else if (live) {
                h0 = grow_g[7 + c * 4 + 0];
                s1 = grow_g[7 + c * 4 + 1] * 0.025f;
                s2 = grow_g[7 + c * 4 + 2] * 0.025f;
                s3 = grow_g[7 + c * 4 + 3] * 0.025f;
            } else {
                h0 = s1 = s2 = s3 = 0.f;
            }
            har[c * 4 + 0] = h0;
#pragma unroll
            for (int i = 0; i < 3; i++) {
                int ri = pr[i];
                har[c * 4 + 1 + i] = cam.c2w[ri * 3 + 1] * s1
                                   + cam.c2w[ri * 3 + 2] * s2
                                   + cam.c2w[ri * 3 + 0] * s3;
            }
        }
    }

    // ---- direct streaming stores: rotations, scales ----
    if (live) {
        __stcs((float4*)rot_o + idx, make_float4(qw, qx, qy, qz));
        __stcs(sc_o + (size_t)idx * 3 + 0, sc0);
        __stcs(sc_o + (size_t)idx * 3 + 1, sc1);
        __stcs(sc_o + (size_t)idx * 3 + 2, sc2);
    }

    // ---- cov = (W R diag(s)) (W R diag(s))^T ----
    float R[9];
    R[0] = 1.f - 2.f * (qy * qy + qz * qz);
    R[1] = 2.f * (qx * qy - qw * qz);
    R[2] = 2.f * (qx * qz + qw * qy);
    R[3] = 2.f * (qx * qy + qw * qz);
    R[4] = 1.f - 2.f * (qx * qx + qz * qz);
    R[5] = 2.f * (qy * qz - qw * qx);
    R[6] = 2.f * (qx * qz - qw * qy);
    R[7] = 2.f * (qy * qz + qw * qx);
    R[8] = 1.f - 2.f * (qx * qx + qy * qy);

    float T[9];
#pragma unroll
    for (int i = 0; i < 3; i++) {
        T[i * 3 + 0] = (cam.c2w[i * 3 + 0] * R[0] + cam.c2w[i * 3 + 1] * R[3]
                      + cam.c2w[i * 3 + 2] * R[6]) * sc0;
        T[i * 3 + 1] = (cam.c2w[i * 3 + 0] * R[1] + cam.c2w[i * 3 + 1] * R[4]
                      + cam.c2w[i * 3 + 2] * R[7]) * sc1;
        T[i * 3 + 2] = (cam.c2w[i * 3 + 0] * R[2] + cam.c2w[i * 3 + 1] * R[5]
                      + cam.c2w[i * 3 + 2] * R[8]) * sc2;
    }
    float cov[9];
#pragma unroll
    for (int i = 0; i < 3; i++)
#pragma unroll
        for (int j = 0; j <= i; j++) {
            float v = T[i * 3 + 0] * T[j * 3 + 0]
                    + T[i * 3 + 1] * T[j * 3 + 1]
                    + T[i * 3 + 2] * T[j * 3 + 2];
            cov[i * 3 + j] = v;
            cov[j * 3 + i] = v;
        }

    if (full) {
        __syncthreads();   // all smem input reads complete; safe to overwrite buf

        // stage cov (scalar, stride 9 odd -> conflict-free)
#pragma unroll
        for (int i = 0; i < 9; i++) buf[tid * 9 + i] = cov[i];
        // stage har (STS.128, float4-stride 3 -> conflict-free)
        {
            float4* h4 = (float4*)(buf + 9 * TPB);
#pragma unroll
            for (int c = 0; c < 3; c++)
                h4[tid * 3 + c] = make_float4(har[c * 4 + 0], har[c * 4 + 1],
                                              har[c * 4 + 2], har[c * 4 + 3]);
        }
        __syncthreads();

        // combined coalesced streaming flush
        const float4* s4 = (const float4*)buf;
        float4* dc = (float4*)(cov_o + (size_t)idx0 * 9);
        for (int j = tid; j < TPB * 9 / 4; j += TPB)  __stcs(dc + j, s4[j]);
        float4* dh = (float4*)(har_o + (size_t)idx0 * 12);
        for (int j = tid; j < TPB * 12 / 4; j += TPB) __stcs(dh + j, s4[TPB * 9 / 4 + j]);
    } else if (live) {
#pragma unroll
        for (int i = 0; i < 9; i++)  __stcs(cov_o + (size_t)idx * 9 + i, cov[i]);
#pragma unroll
        for (int i = 0; i < 12; i++) __stcs(har_o + (size_t)idx * 12 + i, har[i]);
    }
}

extern "C" void kernel_launch(void* const* d_in, const int* in_sizes, int n_in,
                              void* d_out, int out_size)
{
    const float* ext    = (const float*)d_in[0];
    const float* intr   = (const float*)d_in[1];
    const float* coords = (const float*)d_in[2];
    const float* depths = (const float*)d_in[3];
    const float* opac   = (const float*)d_in[4];
    const float* rg     = (const float*)d_in[5];
    const unsigned int* hptr = (const unsigned int*)d_in[6];
    const unsigned int* wptr = (const unsigned int*)d_in[7];
    float* out = (float*)d_out;

    const int B = in_sizes[0] / 16;            // extrinsics: B*1*4*4
    const int N = in_sizes[3] / B;             // depths: B*N

    dim3 grid((N + TPB - 1) / TPB, B);
    mono_gaussian_adapter_kernel<<<grid, TPB>>>(
        ext, intr, coords, depths, opac, rg, hptr, wptr, out, N);
}